// round 2
// baseline (speedup 1.0000x reference)
#include <cuda_runtime.h>
#include <cuda_bf16.h>
#include <math.h>

#define BINS 30
#define HIST_THREADS 256
#define HIST_STRIDE 33          // pad 30 -> 33 words to decorrelate banks
#define LOSS_THREADS 256

// Global scratch: bin histogram (zeroed by a tiny kernel each launch so the
// captured graph is replay-deterministic).
__device__ unsigned int g_hist[BINS];

// ---------------------------------------------------------------------------
// shared math — MUST be identical between pass 1 and pass 2 so the bin index
// recomputation is bit-identical.
// ---------------------------------------------------------------------------
__device__ __forceinline__ int bin_of(float x, float t) {
    float s = 1.0f / (1.0f + expf(-x));
    float g = fabsf(s - t);
    int b = (int)(g * 29.9999f);     // g >= 0, so int-cast == floor
    return b > (BINS - 1) ? (BINS - 1) : b;
}

__device__ __forceinline__ float bce_of(float x, float t) {
    // stable binary_cross_entropy_with_logits
    return fmaxf(x, 0.0f) - x * t + log1pf(expf(-fabsf(x)));
}

// ---------------------------------------------------------------------------
// Kernel 0: zero the global histogram
// ---------------------------------------------------------------------------
__global__ void zero_hist_kernel() {
    if (threadIdx.x < BINS) g_hist[threadIdx.x] = 0u;
}

// ---------------------------------------------------------------------------
// Kernel 1: histogram of gradient-density bins.
// Per-thread private histograms in shared memory (atomic-free hot loop),
// block reduction + 30 global atomicAdds at the end.
// ---------------------------------------------------------------------------
__global__ void __launch_bounds__(HIST_THREADS)
hist_kernel(const float4* __restrict__ logits,
            const int4*  __restrict__ target,
            int n4)
{
    __shared__ unsigned int sh[HIST_THREADS * HIST_STRIDE];
    unsigned int* my = sh + threadIdx.x * HIST_STRIDE;

    #pragma unroll
    for (int i = 0; i < HIST_STRIDE; i++) my[i] = 0u;
    // no sync needed: each thread touches only its own slice until the reduce

    int idx    = blockIdx.x * blockDim.x + threadIdx.x;
    int stride = gridDim.x * blockDim.x;
    for (int i = idx; i < n4; i += stride) {
        float4 x = logits[i];
        int4   t = target[i];
        my[bin_of(x.x, (float)t.x)]++;
        my[bin_of(x.y, (float)t.y)]++;
        my[bin_of(x.z, (float)t.z)]++;
        my[bin_of(x.w, (float)t.w)]++;
    }
    __syncthreads();

    // bins 0..29 reduced by threads 0..29; per-iteration addresses
    // (33*t + b) % 32 == (t + b) % 32 are all-distinct across b -> conflict-free
    if (threadIdx.x < BINS) {
        unsigned int s = 0;
        #pragma unroll 8
        for (int t = 0; t < HIST_THREADS; t++)
            s += sh[t * HIST_STRIDE + threadIdx.x];
        atomicAdd(&g_hist[threadIdx.x], s);
    }
}

// ---------------------------------------------------------------------------
// Kernel 2: one block per row. Recompute bin, gather beta (computed in-block
// from the finalized histogram — kernel boundary is the grid sync),
// weighted stable BCE, block reduction -> row mean.
// ---------------------------------------------------------------------------
__global__ void __launch_bounds__(LOSS_THREADS)
loss_kernel(const float4* __restrict__ logits,
            const int4*  __restrict__ target,
            float* __restrict__ out,
            int cols, float tot)
{
    __shared__ float beta_sh[BINS];
    __shared__ float red[LOSS_THREADS / 32];

    // warp 0 computes beta[30] from the global histogram (L2-resident, cheap)
    if (threadIdx.x < 32) {
        unsigned int c = (threadIdx.x < BINS) ? g_hist[threadIdx.x] : 0u;
        unsigned int nz_mask = __ballot_sync(0xffffffff, c > 0u);
        float nonempty = (float)__popc(nz_mask);
        if (threadIdx.x < BINS) {
            float denom = fmaxf((float)c * nonempty, 1e-4f);
            beta_sh[threadIdx.x] = tot / denom;
        }
    }
    __syncthreads();

    int row = blockIdx.x;
    int c4  = cols >> 2;
    const float4* lrow = logits + (size_t)row * c4;
    const int4*   trow = target + (size_t)row * c4;

    float acc = 0.0f;
    for (int i = threadIdx.x; i < c4; i += LOSS_THREADS) {
        float4 x = lrow[i];
        int4   t = trow[i];
        {
            float tf = (float)t.x;
            acc += beta_sh[bin_of(x.x, tf)] * bce_of(x.x, tf);
        }
        {
            float tf = (float)t.y;
            acc += beta_sh[bin_of(x.y, tf)] * bce_of(x.y, tf);
        }
        {
            float tf = (float)t.z;
            acc += beta_sh[bin_of(x.z, tf)] * bce_of(x.z, tf);
        }
        {
            float tf = (float)t.w;
            acc += beta_sh[bin_of(x.w, tf)] * bce_of(x.w, tf);
        }
    }

    // block reduction: warp shuffle + smem
    #pragma unroll
    for (int off = 16; off > 0; off >>= 1)
        acc += __shfl_down_sync(0xffffffff, acc, off);
    int wid = threadIdx.x >> 5;
    int lid = threadIdx.x & 31;
    if (lid == 0) red[wid] = acc;
    __syncthreads();
    if (wid == 0) {
        float v = (lid < (LOSS_THREADS / 32)) ? red[lid] : 0.0f;
        #pragma unroll
        for (int off = 4; off > 0; off >>= 1)
            v += __shfl_down_sync(0xffffffff, v, off);
        if (lid == 0) out[row] = v / (float)cols;
    }
}

// ---------------------------------------------------------------------------
extern "C" void kernel_launch(void* const* d_in, const int* in_sizes, int n_in,
                              void* d_out, int out_size)
{
    const float* logits = (const float*)d_in[0];
    const int*   target = (const int*)d_in[1];
    float*       out    = (float*)d_out;

    int n    = in_sizes[0];          // 33554432
    int rows = out_size;             // 4096
    int cols = n / rows;             // 8192
    int n4   = n >> 2;

    zero_hist_kernel<<<1, 32>>>();

    // 6 resident blocks/SM (33.8KB smem each) * 148 SMs = one full wave
    int hist_grid = 888;
    hist_kernel<<<hist_grid, HIST_THREADS>>>(
        (const float4*)logits, (const int4*)target, n4);

    loss_kernel<<<rows, LOSS_THREADS>>>(
        (const float4*)logits, (const int4*)target, out, cols, (float)n);
}

// round 3
// speedup vs baseline: 1.2230x; 1.2230x over previous
#include <cuda_runtime.h>
#include <cuda_bf16.h>
#include <math.h>

#define BINS 30
#define P1_THREADS 256
#define MAX_ROWS 8192

// Global scratch (no allocations allowed): per-(bin,row) BCE sums, global counts.
__device__ float        g_S[BINS * MAX_ROWS];   // bin-major: g_S[b*rows + row]
__device__ unsigned int g_cnt[BINS];

// ---------------------------------------------------------------------------
// Pass 1: one block per row. Single read of logits+target.
// Accumulates per-thread-private (sum_bce, count) per bin in shared memory,
// bin-major layout sh[b*256 + tid] -> bank = tid%32 = lane -> conflict-free
// for any data. Epilogue: cross-thread reduce, write S[b][row], atomicAdd counts.
// ---------------------------------------------------------------------------
__global__ void __launch_bounds__(P1_THREADS)
pass1_kernel(const float4* __restrict__ logits,
             const int4*  __restrict__ target,
             int rows, int c4)
{
    __shared__ float         s_sum[BINS * P1_THREADS];   // 30720 B
    __shared__ unsigned char s_cnt[BINS * P1_THREADS];   //  7680 B

    const int tid = threadIdx.x;

    // Zero own column only (i ≡ tid mod 256) -> no sync needed before hot loop.
    #pragma unroll
    for (int b = 0; b < BINS; b++) {
        s_sum[b * P1_THREADS + tid] = 0.0f;
        s_cnt[b * P1_THREADS + tid] = 0;
    }

    const int row = blockIdx.x;
    const float4* lrow = logits + (size_t)row * c4;
    const int4*   trow = target + (size_t)row * c4;

    for (int i = tid; i < c4; i += P1_THREADS) {
        float4 x = lrow[i];
        int4   t = trow[i];

        #pragma unroll
        for (int k = 0; k < 4; k++) {
            float xv = (k == 0) ? x.x : (k == 1) ? x.y : (k == 2) ? x.z : x.w;
            int   tv = (k == 0) ? t.x : (k == 1) ? t.y : (k == 2) ? t.z : t.w;

            float ax   = fabsf(xv);
            float z    = __expf(-ax);              // e^{-|x|}
            float w1   = 1.0f + z;
            float sabs = __fdividef(1.0f, w1);     // sigmoid(|x|)
            // g = |sigmoid(x) - t|; with t in {0,1}:
            //   g = (t==1)==(x>=0) ? 1 - sigmoid(|x|) : sigmoid(|x|)
            bool  flip = (tv != 0) == (xv >= 0.0f);
            float g    = flip ? (1.0f - sabs) : sabs;
            int   b    = (int)(g * 29.9999f);
            b = b > (BINS - 1) ? (BINS - 1) : b;

            // stable BCE: max(x,0) - x*t + log(1 + e^{-|x|})
            float bce = fmaxf(xv, 0.0f) - (tv ? xv : 0.0f) + __logf(w1);

            int slot = b * P1_THREADS + tid;
            s_sum[slot] += bce;
            s_cnt[slot] += 1;
        }
    }
    __syncthreads();

    // Reduce: warp w handles bins w, w+8, w+16, w+24.
    int warp = tid >> 5, lane = tid & 31;
    for (int b = warp; b < BINS; b += (P1_THREADS / 32)) {
        float        fs = 0.0f;
        unsigned int cs = 0;
        #pragma unroll
        for (int k = 0; k < P1_THREADS / 32; k++) {
            int s = b * P1_THREADS + k * 32 + lane;
            fs += s_sum[s];
            cs += (unsigned int)s_cnt[s];
        }
        #pragma unroll
        for (int off = 16; off > 0; off >>= 1) {
            fs += __shfl_down_sync(0xffffffff, fs, off);
            cs += __shfl_down_sync(0xffffffff, cs, off);
        }
        if (lane == 0) {
            g_S[b * rows + row] = fs;
            if (cs) atomicAdd(&g_cnt[b], cs);
        }
    }
}

// ---------------------------------------------------------------------------
// Pass 2: beta from global counts, out[row] = (1/cols) * dot(beta, S[:,row]).
// S is bin-major so lane accesses are coalesced. Tiny (~500KB, L2-resident).
// ---------------------------------------------------------------------------
__global__ void __launch_bounds__(256)
finalize_kernel(float* __restrict__ out, int rows, float inv_cols, float tot)
{
    __shared__ float beta[BINS];
    if (threadIdx.x < 32) {
        unsigned int c = (threadIdx.x < BINS) ? g_cnt[threadIdx.x] : 0u;
        unsigned int nz = __ballot_sync(0xffffffff, c > 0u);
        float nonempty = (float)__popc(nz);
        if (threadIdx.x < BINS)
            beta[threadIdx.x] = tot / fmaxf((float)c * nonempty, 1e-4f);
    }
    __syncthreads();

    int row = blockIdx.x * blockDim.x + threadIdx.x;
    if (row < rows) {
        float acc = 0.0f;
        #pragma unroll
        for (int b = 0; b < BINS; b++)
            acc += beta[b] * g_S[b * rows + row];
        out[row] = acc * inv_cols;
    }
}

// ---------------------------------------------------------------------------
extern "C" void kernel_launch(void* const* d_in, const int* in_sizes, int n_in,
                              void* d_out, int out_size)
{
    const float* logits = (const float*)d_in[0];
    const int*   target = (const int*)d_in[1];
    float*       out    = (float*)d_out;

    int n    = in_sizes[0];          // 33554432
    int rows = out_size;             // 4096
    int cols = n / rows;             // 8192
    int c4   = cols >> 2;

    // Reset global counts (async memset: one less kernel launch, capturable).
    void* cnt_ptr = nullptr;
    cudaGetSymbolAddress(&cnt_ptr, g_cnt);
    cudaMemsetAsync(cnt_ptr, 0, BINS * sizeof(unsigned int), 0);

    pass1_kernel<<<rows, P1_THREADS>>>(
        (const float4*)logits, (const int4*)target, rows, c4);

    finalize_kernel<<<(rows + 255) / 256, 256>>>(
        out, rows, 1.0f / (float)cols, (float)n);
}